// round 2
// baseline (speedup 1.0000x reference)
#include <cuda_runtime.h>
#include <cuda_bf16.h>
#include <math.h>

#define N_NODES 65536
#define N_EDGES 1048576
#define IN_FEATS 128
#define N_HIDDEN 64

// ---------------- device scratch (no allocations allowed) ----------------
__device__ float g_h [N_NODES * N_HIDDEN];
__device__ float g_h2[N_NODES * N_HIDDEN];
__device__ float g_inv[N_NODES];
__device__ int   g_deg[N_NODES];
__device__ int   g_rowptr[N_NODES + 1];
__device__ int   g_cursor[N_NODES];
__device__ int   g_bsum[256];
__device__ int   g_boff[256];
__device__ int   g_csrc[N_EDGES];

// ---------------- CSR build ----------------
__global__ void k_zero_deg() {
    int i = blockIdx.x * blockDim.x + threadIdx.x;
    if (i < N_NODES) g_deg[i] = 0;
}

__global__ void k_hist(const int* __restrict__ dst) {
    int i = blockIdx.x * blockDim.x + threadIdx.x;
    if (i < N_EDGES) atomicAdd(&g_deg[dst[i]], 1);
}

__global__ void k_blocksum() {
    __shared__ int sh[256];
    int i = blockIdx.x * 256 + threadIdx.x;
    sh[threadIdx.x] = g_deg[i];
    __syncthreads();
    for (int o = 128; o; o >>= 1) {
        if (threadIdx.x < o) sh[threadIdx.x] += sh[threadIdx.x + o];
        __syncthreads();
    }
    if (threadIdx.x == 0) g_bsum[blockIdx.x] = sh[0];
}

__global__ void k_scan_bsum() {
    __shared__ int sh[256];
    int t = threadIdx.x;
    sh[t] = g_bsum[t];
    __syncthreads();
    for (int off = 1; off < 256; off <<= 1) {
        int v = (t >= off) ? sh[t - off] : 0;
        __syncthreads();
        sh[t] += v;
        __syncthreads();
    }
    g_boff[t] = (t == 0) ? 0 : sh[t - 1];
}

__global__ void k_fill_rowptr() {
    __shared__ int sh[256];
    int t = threadIdx.x;
    int i = blockIdx.x * 256 + t;
    int d = g_deg[i];
    sh[t] = d;
    __syncthreads();
    for (int off = 1; off < 256; off <<= 1) {
        int v = (t >= off) ? sh[t - off] : 0;
        __syncthreads();
        sh[t] += v;
        __syncthreads();
    }
    int excl = g_boff[blockIdx.x] + sh[t] - d;
    g_rowptr[i] = excl;
    g_cursor[i] = excl;
    if (i == N_NODES - 1) g_rowptr[N_NODES] = N_EDGES;
}

__global__ void k_scatter(const int* __restrict__ src, const int* __restrict__ dst) {
    int i = blockIdx.x * blockDim.x + threadIdx.x;
    if (i < N_EDGES) {
        int p = atomicAdd(&g_cursor[dst[i]], 1);
        g_csrc[p] = src[i];
    }
}

// ---------------- per-node inverse L2 norm (warp per node) ----------------
__global__ void k_norm(const float* __restrict__ h) {
    int w = (blockIdx.x * blockDim.x + threadIdx.x) >> 5;
    int lane = threadIdx.x & 31;
    if (w >= N_NODES) return;
    float2 v = ((const float2*)(h + (size_t)w * N_HIDDEN))[lane];
    float p = v.x * v.x + v.y * v.y;
    #pragma unroll
    for (int o = 16; o; o >>= 1) p += __shfl_xor_sync(0xffffffffu, p, o);
    if (lane == 0) g_inv[w] = 1.0f / fmaxf(sqrtf(p), 1e-12f);
}

// ---------------- AGNN edge kernel: warp per dst node, online softmax ----------------
__global__ void k_edge(const float* __restrict__ h,
                       const float* __restrict__ betas, int layer,
                       float* __restrict__ out) {
    int n = (blockIdx.x * blockDim.x + threadIdx.x) >> 5;
    int lane = threadIdx.x & 31;
    if (n >= N_NODES) return;

    int start = g_rowptr[n];
    int end   = g_rowptr[n + 1];

    float2 acc = make_float2(0.f, 0.f);
    if (start < end) {
        float beta = betas[layer];
        float2 hd = ((const float2*)(h + (size_t)n * N_HIDDEN))[lane];
        float bid = beta * g_inv[n];

        float m = -3.0e38f;
        float s = 0.f;

        // software pipeline: prefetch next edge's source row
        int   srcn = g_csrc[start];
        float2 hsn = ((const float2*)(h + (size_t)srcn * N_HIDDEN))[lane];
        float invn_ = g_inv[srcn];

        for (int k = start; k < end; k++) {
            float2 hs   = hsn;
            float  invs = invn_;
            if (k + 1 < end) {
                int s2 = g_csrc[k + 1];
                hsn   = ((const float2*)(h + (size_t)s2 * N_HIDDEN))[lane];
                invn_ = g_inv[s2];
            }
            float p = hs.x * hd.x + hs.y * hd.y;
            #pragma unroll
            for (int o = 16; o; o >>= 1) p += __shfl_xor_sync(0xffffffffu, p, o);
            float e = bid * invs * p;

            float nm    = fmaxf(m, e);
            float scale = __expf(m - nm);  // 0 on first iteration
            float ex    = __expf(e - nm);
            s     = s * scale + ex;
            acc.x = acc.x * scale + ex * hs.x;
            acc.y = acc.y * scale + ex * hs.y;
            m = nm;
        }
        float rs = 1.0f / s;
        acc.x *= rs;
        acc.y *= rs;
    }
    ((float2*)(out + (size_t)n * N_HIDDEN))[lane] = acc;
}

// ---------------- tiled fp32 GEMM: C[M,64] = act(A[M,K] @ B[K,64] + bias) ----------------
template<int K, bool RELU>
__global__ void k_gemm(const float* __restrict__ A, const float* __restrict__ B,
                       const float* __restrict__ bias, float* __restrict__ C) {
    __shared__ float As[32][68];   // [k][row], padded
    __shared__ float Bs[32][64];   // [k][col]

    int tid = threadIdx.x;          // 256 threads
    int tx = tid & 15;              // col group (4 cols)
    int ty = tid >> 4;              // row group (4 rows)
    int row0 = blockIdx.x * 64;

    float acc[4][4];
    #pragma unroll
    for (int i = 0; i < 4; i++)
        #pragma unroll
        for (int j = 0; j < 4; j++) acc[i][j] = 0.f;

    for (int k0 = 0; k0 < K; k0 += 32) {
        // A tile: 64 rows x 32 k  -> transposed into As[k][row]
        #pragma unroll
        for (int it = 0; it < 2; it++) {
            int idx = tid + it * 256;      // float4 index, 0..511
            int r  = idx >> 3;             // 8 float4 per row
            int kc = (idx & 7) * 4;
            float4 v = *(const float4*)(A + (size_t)(row0 + r) * K + k0 + kc);
            As[kc + 0][r] = v.x;
            As[kc + 1][r] = v.y;
            As[kc + 2][r] = v.z;
            As[kc + 3][r] = v.w;
        }
        // B tile: 32 k x 64 cols, contiguous
        #pragma unroll
        for (int it = 0; it < 2; it++) {
            int idx = tid + it * 256;
            int kk = idx >> 4;             // 16 float4 per row of 64
            int cc = (idx & 15) * 4;
            *(float4*)&Bs[kk][cc] = *(const float4*)(B + (size_t)(k0 + kk) * 64 + cc);
        }
        __syncthreads();

        #pragma unroll
        for (int k = 0; k < 32; k++) {
            float4 av = *(const float4*)&As[k][ty * 4];
            float4 bv = *(const float4*)&Bs[k][tx * 4];
            float a[4] = {av.x, av.y, av.z, av.w};
            float b[4] = {bv.x, bv.y, bv.z, bv.w};
            #pragma unroll
            for (int i = 0; i < 4; i++)
                #pragma unroll
                for (int j = 0; j < 4; j++)
                    acc[i][j] += a[i] * b[j];
        }
        __syncthreads();
    }

    #pragma unroll
    for (int i = 0; i < 4; i++) {
        int r = row0 + ty * 4 + i;
        float4 o;
        float* po = (float*)&o;
        #pragma unroll
        for (int j = 0; j < 4; j++) {
            float v = acc[i][j] + bias[tx * 4 + j];
            if (RELU) v = fmaxf(v, 0.f);
            po[j] = v;
        }
        *(float4*)(C + (size_t)r * 64 + tx * 4) = o;
    }
}

// ---------------- launch ----------------
extern "C" void kernel_launch(void* const* d_in, const int* in_sizes, int n_in,
                              void* d_out, int out_size) {
    const float* features = (const float*)d_in[0];
    const int*   src      = (const int*)  d_in[1];
    const int*   dst      = (const int*)  d_in[2];
    const float* W1       = (const float*)d_in[3];
    const float* b1       = (const float*)d_in[4];
    const float* W2       = (const float*)d_in[5];
    const float* b2       = (const float*)d_in[6];
    const float* betas    = (const float*)d_in[7];
    float* out = (float*)d_out;

    float *h = nullptr, *h2 = nullptr;
    cudaGetSymbolAddress((void**)&h,  g_h);
    cudaGetSymbolAddress((void**)&h2, g_h2);

    // 1) projection: h = relu(features @ W1 + b1)
    k_gemm<IN_FEATS, true><<<N_NODES / 64, 256>>>(features, W1, b1, h);

    // 2) CSR build (by dst)
    k_zero_deg<<<N_NODES / 256, 256>>>();
    k_hist<<<N_EDGES / 256, 256>>>(dst);
    k_blocksum<<<256, 256>>>();
    k_scan_bsum<<<1, 256>>>();
    k_fill_rowptr<<<256, 256>>>();
    k_scatter<<<N_EDGES / 256, 256>>>(src, dst);

    // 3) AGNN layer 0: h -> h2
    k_norm<<<N_NODES / 8, 256>>>(h);
    k_edge<<<N_NODES / 8, 256>>>(h, betas, 0, h2);

    // 4) AGNN layer 1: h2 -> h
    k_norm<<<N_NODES / 8, 256>>>(h2);
    k_edge<<<N_NODES / 8, 256>>>(h2, betas, 1, h);

    // 5) classifier: out = h @ W2 + b2
    k_gemm<N_HIDDEN, false><<<N_NODES / 64, 256>>>(h, W2, b2, out);
}

// round 3
// speedup vs baseline: 1.1074x; 1.1074x over previous
#include <cuda_runtime.h>
#include <cuda_bf16.h>
#include <math.h>
#include <stdint.h>

#define N_NODES 65536
#define N_EDGES 1048576
#define IN_FEATS 128
#define N_HIDDEN 64

// ---------------- device scratch (no allocations allowed) ----------------
__device__ float g_h  [N_NODES * N_HIDDEN];
__device__ float g_h2 [N_NODES * N_HIDDEN];
__device__ float g_invA[N_NODES];
__device__ float g_invB[N_NODES];
__device__ int   g_deg[N_NODES];
__device__ int   g_rowptr[N_NODES + 4];
__device__ int   g_cursor[N_NODES];
__device__ int   g_csrc[N_EDGES];

// ---------------- packed f32x2 helpers ----------------
__device__ __forceinline__ uint64_t pack2(float x, float y) {
    uint64_t r; asm("mov.b64 %0, {%1, %2};" : "=l"(r) : "f"(x), "f"(y)); return r;
}
__device__ __forceinline__ uint64_t dup2(float x) {
    uint64_t r; asm("mov.b64 %0, {%1, %1};" : "=l"(r) : "f"(x)); return r;
}
__device__ __forceinline__ void fma2(uint64_t& d, uint64_t a, uint64_t b) {
    asm("fma.rn.f32x2 %0, %1, %2, %0;" : "+l"(d) : "l"(a), "l"(b));
}
__device__ __forceinline__ void unpack2(uint64_t p, float& x, float& y) {
    asm("mov.b64 {%0, %1}, %2;" : "=f"(x), "=f"(y) : "l"(p));
}

// ---------------- GEMM: C[M,64] = act(A[M,K] @ B[K,64] + bias), f32x2 ----------------
// block tile 128 rows x 64 cols, 256 threads, thread = 8 rows x 4 cols
template<int K, bool RELU>
__global__ void k_gemm(const float* __restrict__ A, const float* __restrict__ B,
                       const float* __restrict__ bias, float* __restrict__ C,
                       int do_zero) {
    __shared__ float As[32][132];   // [k][row], pad 132 (mult of 4 -> float4 ok)
    __shared__ float Bs[32][64];

    int tid = threadIdx.x;
    if (do_zero) {                  // fold g_deg zeroing into GEMM1
        int z = blockIdx.x * 256 + tid;
        if (z < N_NODES) g_deg[z] = 0;
    }

    int tx = tid & 15;              // 4 cols
    int ty = tid >> 4;              // 8 rows
    long row0 = (long)blockIdx.x * 128;

    uint64_t acc[4][4];             // [row-pair][col]
    #pragma unroll
    for (int p = 0; p < 4; p++)
        #pragma unroll
        for (int j = 0; j < 4; j++) acc[p][j] = 0ull;

    for (int k0 = 0; k0 < K; k0 += 32) {
        // A tile: 128 rows x 32 k, transposed into As[k][row]
        #pragma unroll
        for (int it = 0; it < 4; it++) {
            int idx = tid + it * 256;          // float4 unit, 0..1023
            int r  = idx >> 3;
            int kc = (idx & 7) << 2;
            float4 v = *(const float4*)(A + (row0 + r) * K + k0 + kc);
            As[kc + 0][r] = v.x;
            As[kc + 1][r] = v.y;
            As[kc + 2][r] = v.z;
            As[kc + 3][r] = v.w;
        }
        // B tile: 32 k x 64 cols
        #pragma unroll
        for (int it = 0; it < 2; it++) {
            int idx = tid + it * 256;
            int kk = idx >> 4;
            int cc = (idx & 15) << 2;
            *(float4*)&Bs[kk][cc] = *(const float4*)(B + (size_t)(k0 + kk) * 64 + cc);
        }
        __syncthreads();

        #pragma unroll
        for (int k = 0; k < 32; k++) {
            float4 a01 = *(const float4*)&As[k][ty * 8];
            float4 a23 = *(const float4*)&As[k][ty * 8 + 4];
            float4 bv  = *(const float4*)&Bs[k][tx * 4];
            uint64_t ap[4];
            ap[0] = pack2(a01.x, a01.y);
            ap[1] = pack2(a01.z, a01.w);
            ap[2] = pack2(a23.x, a23.y);
            ap[3] = pack2(a23.z, a23.w);
            uint64_t bd[4];
            bd[0] = dup2(bv.x); bd[1] = dup2(bv.y);
            bd[2] = dup2(bv.z); bd[3] = dup2(bv.w);
            #pragma unroll
            for (int p = 0; p < 4; p++)
                #pragma unroll
                for (int j = 0; j < 4; j++)
                    fma2(acc[p][j], ap[p], bd[j]);
        }
        __syncthreads();
    }

    float4 bb = *(const float4*)(bias + tx * 4);
    float bbv[4] = {bb.x, bb.y, bb.z, bb.w};
    #pragma unroll
    for (int p = 0; p < 4; p++) {
        long r0 = row0 + ty * 8 + 2 * p;
        float o0[4], o1[4];
        #pragma unroll
        for (int j = 0; j < 4; j++) {
            float lo, hi;
            unpack2(acc[p][j], lo, hi);
            lo += bbv[j]; hi += bbv[j];
            if (RELU) { lo = fmaxf(lo, 0.f); hi = fmaxf(hi, 0.f); }
            o0[j] = lo; o1[j] = hi;
        }
        *(float4*)(C + r0 * 64 + tx * 4)       = make_float4(o0[0], o0[1], o0[2], o0[3]);
        *(float4*)(C + (r0 + 1) * 64 + tx * 4) = make_float4(o1[0], o1[1], o1[2], o1[3]);
    }
}

// ---------------- fused histogram + inv-norm of h ----------------
// grid 4096 x 256: thread i does one edge-histogram atomic;
// 16 lanes per node compute inv L2 norm of h rows (1M threads / 16 = 65536 nodes)
__global__ void k_hist_norm(const int* __restrict__ dst, const float* __restrict__ h) {
    int i = blockIdx.x * 256 + threadIdx.x;
    atomicAdd(&g_deg[dst[i]], 1);

    int n  = i >> 4;
    int l16 = threadIdx.x & 15;
    float4 v = ((const float4*)h)[(size_t)n * 16 + l16];
    float q = v.x * v.x + v.y * v.y + v.z * v.z + v.w * v.w;
    #pragma unroll
    for (int o = 8; o; o >>= 1) q += __shfl_xor_sync(0xffffffffu, q, o);
    if (l16 == 0) g_invA[n] = 1.0f / fmaxf(sqrtf(q), 1e-12f);
}

// ---------------- single-block exclusive scan of g_deg -> rowptr, cursor ----------------
__global__ void k_scan() {
    __shared__ int wsum[32];
    int t = threadIdx.x;            // 1024 threads, 64 elements each
    int base = t * 64;
    const int4* dp = (const int4*)(g_deg + base);

    int sum = 0;
    #pragma unroll
    for (int i = 0; i < 16; i++) { int4 v = dp[i]; sum += v.x + v.y + v.z + v.w; }

    int lane = t & 31, wid = t >> 5;
    int x = sum;
    #pragma unroll
    for (int o = 1; o < 32; o <<= 1) {
        int y = __shfl_up_sync(0xffffffffu, x, o);
        if (lane >= o) x += y;
    }
    if (lane == 31) wsum[wid] = x;
    __syncthreads();
    if (wid == 0) {
        int v = wsum[lane];
        #pragma unroll
        for (int o = 1; o < 32; o <<= 1) {
            int y = __shfl_up_sync(0xffffffffu, v, o);
            if (lane >= o) v += y;
        }
        wsum[lane] = v;
    }
    __syncthreads();
    int run = x - sum + (wid ? wsum[wid - 1] : 0);   // thread-exclusive prefix

    #pragma unroll
    for (int i = 0; i < 16; i++) {
        int4 v = dp[i];
        int4 r;
        r.x = run;
        r.y = r.x + v.x;
        r.z = r.y + v.y;
        r.w = r.z + v.z;
        run = r.w + v.w;
        ((int4*)(g_rowptr + base))[i] = r;
        ((int4*)(g_cursor + base))[i] = r;
    }
    if (t == 1023) g_rowptr[N_NODES] = N_EDGES;
}

__global__ void k_scatter(const int* __restrict__ src, const int* __restrict__ dst) {
    int i = blockIdx.x * 256 + threadIdx.x;
    int p = atomicAdd(&g_cursor[dst[i]], 1);
    g_csrc[p] = src[i];
}

// ---------------- AGNN edge kernel: 8 lanes per dst node, online softmax ----------------
__global__ void k_edge(const float* __restrict__ h, const float* __restrict__ betas,
                       int layer, float* __restrict__ out,
                       const float* __restrict__ invin, float* __restrict__ invout) {
    int gid = blockIdx.x * 256 + threadIdx.x;
    int n   = gid >> 3;                       // node (4 per warp)
    int sl  = threadIdx.x & 7;                // sub-lane within node group
    int lane = threadIdx.x & 31;
    unsigned smask = 0xFFu << (lane & 24);    // this subgroup's 8 lanes

    int start = g_rowptr[n];
    int end   = g_rowptr[n + 1];

    const float4* h4 = (const float4*)h;
    size_t hb = (size_t)n * 16 + sl * 2;
    float4 hd0 = h4[hb], hd1 = h4[hb + 1];

    float4 a0 = make_float4(0.f, 0.f, 0.f, 0.f);
    float4 a1 = make_float4(0.f, 0.f, 0.f, 0.f);

    if (start < end) {
        float bid = betas[layer] * invin[n];
        float m = -3.0e38f, s = 0.f;

        int srcn = g_csrc[start];
        size_t sb = (size_t)srcn * 16 + sl * 2;
        float4 p0 = h4[sb], p1 = h4[sb + 1];
        float invn = invin[srcn];

        for (int k = start; k < end; k++) {
            float4 hs0 = p0, hs1 = p1;
            float  invs = invn;
            if (k + 1 < end) {
                int s2 = g_csrc[k + 1];
                size_t b2 = (size_t)s2 * 16 + sl * 2;
                p0 = h4[b2]; p1 = h4[b2 + 1];
                invn = invin[s2];
            }
            float p = hs0.x * hd0.x + hs0.y * hd0.y + hs0.z * hd0.z + hs0.w * hd0.w
                    + hs1.x * hd1.x + hs1.y * hd1.y + hs1.z * hd1.z + hs1.w * hd1.w;
            p += __shfl_xor_sync(smask, p, 4);
            p += __shfl_xor_sync(smask, p, 2);
            p += __shfl_xor_sync(smask, p, 1);

            float e  = bid * invs * p;
            float nm = fmaxf(m, e);
            float sc = __expf(m - nm);        // 0 on first iteration
            float ex = __expf(e - nm);
            s = s * sc + ex;
            a0.x = a0.x * sc + ex * hs0.x;
            a0.y = a0.y * sc + ex * hs0.y;
            a0.z = a0.z * sc + ex * hs0.z;
            a0.w = a0.w * sc + ex * hs0.w;
            a1.x = a1.x * sc + ex * hs1.x;
            a1.y = a1.y * sc + ex * hs1.y;
            a1.z = a1.z * sc + ex * hs1.z;
            a1.w = a1.w * sc + ex * hs1.w;
            m = nm;
        }
        float rs = 1.0f / s;
        a0.x *= rs; a0.y *= rs; a0.z *= rs; a0.w *= rs;
        a1.x *= rs; a1.y *= rs; a1.z *= rs; a1.w *= rs;
    }

    ((float4*)out)[hb]     = a0;
    ((float4*)out)[hb + 1] = a1;

    if (invout) {   // fused inv-norm of the produced row (feeds next layer)
        float q = a0.x * a0.x + a0.y * a0.y + a0.z * a0.z + a0.w * a0.w
                + a1.x * a1.x + a1.y * a1.y + a1.z * a1.z + a1.w * a1.w;
        q += __shfl_xor_sync(0xffffffffu, q, 4);
        q += __shfl_xor_sync(0xffffffffu, q, 2);
        q += __shfl_xor_sync(0xffffffffu, q, 1);
        if (sl == 0) invout[n] = 1.0f / fmaxf(sqrtf(q), 1e-12f);
    }
}

// ---------------- launch ----------------
extern "C" void kernel_launch(void* const* d_in, const int* in_sizes, int n_in,
                              void* d_out, int out_size) {
    const float* features = (const float*)d_in[0];
    const int*   src      = (const int*)  d_in[1];
    const int*   dst      = (const int*)  d_in[2];
    const float* W1       = (const float*)d_in[3];
    const float* b1       = (const float*)d_in[4];
    const float* W2       = (const float*)d_in[5];
    const float* b2       = (const float*)d_in[6];
    const float* betas    = (const float*)d_in[7];
    float* out = (float*)d_out;

    float *h = nullptr, *h2 = nullptr, *invA = nullptr, *invB = nullptr;
    cudaGetSymbolAddress((void**)&h,    g_h);
    cudaGetSymbolAddress((void**)&h2,   g_h2);
    cudaGetSymbolAddress((void**)&invA, g_invA);
    cudaGetSymbolAddress((void**)&invB, g_invB);

    // 1) projection h = relu(features @ W1 + b1); also zeros g_deg
    k_gemm<IN_FEATS, true><<<N_NODES / 128, 256>>>(features, W1, b1, h, 1);

    // 2) edge histogram + inv-norms of h
    k_hist_norm<<<N_EDGES / 256, 256>>>(dst, h);

    // 3) exclusive scan -> rowptr, cursor
    k_scan<<<1, 1024>>>();

    // 4) CSR scatter
    k_scatter<<<N_EDGES / 256, 256>>>(src, dst);

    // 5) AGNN layer 0: h -> h2 (also writes invB for layer 1)
    k_edge<<<N_NODES * 8 / 256, 256>>>(h, betas, 0, h2, invA, invB);

    // 6) AGNN layer 1: h2 -> h
    k_edge<<<N_NODES * 8 / 256, 256>>>(h2, betas, 1, h, invB, nullptr);

    // 7) classifier: out = h @ W2 + b2
    k_gemm<N_HIDDEN, false><<<N_NODES / 128, 256>>>(h, W2, b2, out, 0);
}